// round 10
// baseline (speedup 1.0000x reference)
#include <cuda_runtime.h>
#include <cstdint>
#include <cstddef>

#define BB 256
#define SS 256
#define EE 128
#define HH 512
#define G4 2048
#define NEGINF (-1e9f)
#define NBLK 256
#define NTHR 256

// ---------------- static device scratch ----------------
__device__ float d_h[BB*HH];
__device__ float d_c[BB*HH];
__device__ float d_gpA[BB*G4];         // gates split-k partial (k-half 0)
__device__ float d_gpB[BB*G4];         // gates split-k partial (k-half 1)
__device__ float d_encout[BB*SS*HH];
__device__ float d_glref[BB*SS*HH];
__device__ float d_ptref[BB*SS*HH];
__device__ float d_qpart[8*BB*HH];     // split-k partials for q projections
__device__ float d_qv[BB*HH];
__device__ float d_decin[BB*EE];
__device__ int   d_alive[BB*SS];
__device__ unsigned d_barcnt;
__device__ unsigned d_bargen;

__device__ __forceinline__ float sigm(float x){ return 1.0f/(1.0f+expf(-x)); }

__device__ __forceinline__ uint32_t s2u(const void* p){
  uint32_t r;
  asm("{ .reg .u64 t; cvta.to.shared.u64 t, %1; cvt.u32.u64 %0, t; }" : "=r"(r) : "l"(p));
  return r;
}

#define MBINIT(a,c)  asm volatile("mbarrier.init.shared.b64 [%0], %1;" :: "r"(a), "r"(c) : "memory")
#define MBINVAL(a)   asm volatile("mbarrier.inval.shared.b64 [%0];" :: "r"(a) : "memory")
#define MBEXPECT(a,b) asm volatile("mbarrier.arrive.expect_tx.shared.b64 _, [%0], %1;" :: "r"(a), "r"(b) : "memory")
#define BULK_G2S(dst,src,bytes,mbar) \
  asm volatile("cp.async.bulk.shared::cluster.global.mbarrier::complete_tx::bytes [%0], [%1], %2, [%3];" \
               :: "r"(dst), "l"(src), "r"(bytes), "r"(mbar) : "memory")

__device__ __forceinline__ void mbwait(uint32_t a, uint32_t ph){
  uint32_t done;
  asm volatile("{ .reg .pred p; mbarrier.try_wait.parity.acquire.cta.shared::cta.b64 p, [%1], %2; selp.b32 %0,1,0,p; }"
               : "=r"(done) : "r"(a), "r"(ph) : "memory");
  while(!done){
    asm volatile("{ .reg .pred p; mbarrier.try_wait.parity.acquire.cta.shared::cta.b64 p, [%1], %2, 0x989680; selp.b32 %0,1,0,p; }"
                 : "=r"(done) : "r"(a), "r"(ph) : "memory");
  }
}

// Threefry-2x32, 20 rounds (JAX constants)
__device__ __forceinline__ void tf2x32(uint32_t k0, uint32_t k1, uint32_t x0, uint32_t x1,
                                       uint32_t &o0, uint32_t &o1){
  uint32_t k2 = k0 ^ k1 ^ 0x1BD11BDAu;
#define TFR(r) { x0 += x1; x1 = (x1<<(r)) | (x1>>(32-(r))); x1 ^= x0; }
  x0 += k0; x1 += k1;
  TFR(13) TFR(15) TFR(26) TFR(6)
  x0 += k1; x1 += k2 + 1u;
  TFR(17) TFR(29) TFR(16) TFR(24)
  x0 += k2; x1 += k0 + 2u;
  TFR(13) TFR(15) TFR(26) TFR(6)
  x0 += k0; x1 += k1 + 3u;
  TFR(17) TFR(29) TFR(16) TFR(24)
  x0 += k1; x1 += k2 + 4u;
  TFR(13) TFR(15) TFR(26) TFR(6)
  x0 += k2; x1 += k0 + 5u;
#undef TFR
  o0 = x0; o1 = x1;
}

// ---------------- grid-wide barrier ----------------
__device__ __forceinline__ void gridsync(){
  __syncthreads();
  if(threadIdx.x==0){
    unsigned g = *(volatile unsigned*)&d_bargen;
    __threadfence();
    unsigned prev = atomicAdd(&d_barcnt, 1u);
    if(prev == NBLK-1u){
      atomicExch(&d_barcnt, 0u);
      __threadfence();
      atomicExch(&d_bargen, g+1u);
    } else {
      while(*(volatile unsigned*)&d_bargen == g) __nanosleep(32);
      __threadfence();
    }
  }
  __syncthreads();
}

// ---------------- 64x64 tile GEMM (refs), prefetched ----------------
__device__ __forceinline__ void gemm_tile(const float* __restrict__ A, const float* __restrict__ W,
                                          const float* __restrict__ bias, float* __restrict__ C,
                                          long m0, int n0, float* As, float* Ws){
  const int tid  = threadIdx.x;
  const int arow = tid>>2, akq = tid&3;
  const int tx   = tid&15, ty  = tid>>4;
  float acc[4][4];
#pragma unroll
  for(int i=0;i<4;i++)
#pragma unroll
    for(int j=0;j<4;j++) acc[i][j]=0.0f;

  float4 a = *(const float4*)(A + (size_t)(m0+arow)*HH + akq*4);
  float4 w = *(const float4*)(W + (size_t)(n0+arow)*HH + akq*4);
  for(int k0=0;k0<HH;k0+=16){
    As[(akq*4+0)*68+arow]=a.x; As[(akq*4+1)*68+arow]=a.y; As[(akq*4+2)*68+arow]=a.z; As[(akq*4+3)*68+arow]=a.w;
    Ws[(akq*4+0)*68+arow]=w.x; Ws[(akq*4+1)*68+arow]=w.y; Ws[(akq*4+2)*68+arow]=w.z; Ws[(akq*4+3)*68+arow]=w.w;
    __syncthreads();
    if(k0+16<HH){
      a = *(const float4*)(A + (size_t)(m0+arow)*HH + k0+16 + akq*4);
      w = *(const float4*)(W + (size_t)(n0+arow)*HH + k0+16 + akq*4);
    }
#pragma unroll
    for(int kk=0;kk<16;kk++){
      float4 av = *(const float4*)&As[kk*68+tx*4];
      float4 wv = *(const float4*)&Ws[kk*68+ty*4];
      acc[0][0]+=av.x*wv.x; acc[0][1]+=av.x*wv.y; acc[0][2]+=av.x*wv.z; acc[0][3]+=av.x*wv.w;
      acc[1][0]+=av.y*wv.x; acc[1][1]+=av.y*wv.y; acc[1][2]+=av.y*wv.z; acc[1][3]+=av.y*wv.w;
      acc[2][0]+=av.z*wv.x; acc[2][1]+=av.z*wv.y; acc[2][2]+=av.z*wv.z; acc[2][3]+=av.z*wv.w;
      acc[3][0]+=av.w*wv.x; acc[3][1]+=av.w*wv.y; acc[3][2]+=av.w*wv.z; acc[3][3]+=av.w*wv.w;
    }
    __syncthreads();
  }
  const int n = n0 + ty*4;
  float b0=bias[n+0], b1=bias[n+1], b2=bias[n+2], b3=bias[n+3];
#pragma unroll
  for(int i=0;i<4;i++){
    float4 o; o.x=acc[i][0]+b0; o.y=acc[i][1]+b1; o.z=acc[i][2]+b2; o.w=acc[i][3]+b3;
    *(float4*)(C + (size_t)(m0+tx*4+i)*HH + n) = o;
  }
}

// ---------------- q-projection split-k8: 256 blocks, 64x64 tile, k-slice 64 ----------------
__device__ __forceinline__ void gemm_qk8(const float* __restrict__ A, const float* __restrict__ W,
                                         float* As, float* Ws){
  const int tid  = threadIdx.x;
  const int bx   = blockIdx.x;
  const int tt   = bx & 31, kh = bx >> 5;
  const int m0   = (tt>>3)*64, n0 = (tt&7)*64;
  const int kb   = kh*64;
  const int arow = tid>>2, akq = tid&3;
  const int tx   = tid&15, ty  = tid>>4;
  float acc[4][4];
#pragma unroll
  for(int i=0;i<4;i++)
#pragma unroll
    for(int j=0;j<4;j++) acc[i][j]=0.0f;

  for(int k0=kb;k0<kb+64;k0+=16){
    float4 a = *(const float4*)(A + (size_t)(m0+arow)*HH + k0 + akq*4);
    float4 w = *(const float4*)(W + (size_t)(n0+arow)*HH + k0 + akq*4);
    As[(akq*4+0)*68+arow]=a.x; As[(akq*4+1)*68+arow]=a.y; As[(akq*4+2)*68+arow]=a.z; As[(akq*4+3)*68+arow]=a.w;
    Ws[(akq*4+0)*68+arow]=w.x; Ws[(akq*4+1)*68+arow]=w.y; Ws[(akq*4+2)*68+arow]=w.z; Ws[(akq*4+3)*68+arow]=w.w;
    __syncthreads();
#pragma unroll
    for(int kk=0;kk<16;kk++){
      float4 av = *(const float4*)&As[kk*68+tx*4];
      float4 wv = *(const float4*)&Ws[kk*68+ty*4];
      acc[0][0]+=av.x*wv.x; acc[0][1]+=av.x*wv.y; acc[0][2]+=av.x*wv.z; acc[0][3]+=av.x*wv.w;
      acc[1][0]+=av.y*wv.x; acc[1][1]+=av.y*wv.y; acc[1][2]+=av.y*wv.z; acc[1][3]+=av.y*wv.w;
      acc[2][0]+=av.z*wv.x; acc[2][1]+=av.z*wv.y; acc[2][2]+=av.z*wv.z; acc[2][3]+=av.z*wv.w;
      acc[3][0]+=av.w*wv.x; acc[3][1]+=av.w*wv.y; acc[3][2]+=av.w*wv.z; acc[3][3]+=av.w*wv.w;
    }
    __syncthreads();
  }
  float* P = d_qpart + (size_t)kh*(BB*HH);
  const int n = n0 + ty*4;
#pragma unroll
  for(int i=0;i<4;i++){
    float4 o; o.x=acc[i][0]; o.y=acc[i][1]; o.z=acc[i][2]; o.w=acc[i][3];
    *(float4*)(P + (size_t)(m0+tx*4+i)*HH + n) = o;
  }
}

__device__ __forceinline__ float qcombine(int b, int e, const float* __restrict__ bias){
  float v = d_qpart[(size_t)b*HH + e];
#pragma unroll
  for(int kh=1;kh<8;kh++) v += d_qpart[(size_t)kh*(BB*HH) + (size_t)b*HH + e];
  return v + bias[e];
}

// ---------------- gates GEMM split-k2: 256 blocks, 64x64 tile ----------------
// block bx: tile tt=bx&127 (c=tt&31, m0=(tt>>5)*64), kh=bx>>7
// kh=0: Whh k in [0,320) ; kh=1: Whh k in [320,512) + Wih k in [0,128). 320 each.
// partial written in gate-major layout: P[row*2048 + gate*512 + j]
__device__ __forceinline__ void gates_part(const float* __restrict__ Whh, const float* __restrict__ Wih,
                                           const float* __restrict__ embedding,
                                           const int* __restrict__ inputs, int t,
                                           float* As, float* Ws, int* cities){
  const int tid  = threadIdx.x;
  const int tt   = blockIdx.x & 127;
  const int kh   = blockIdx.x >> 7;
  const int c    = tt & 31;
  const int m0   = (tt >> 5) * 64;
  const int arow = tid>>2, akq = tid&3;
  const int tx   = tid&15, ty  = tid>>4;
  const int wrow = ((arow>>4)*512) + c*16 + (arow&15);
  float acc[4][4];
#pragma unroll
  for(int i=0;i<4;i++)
#pragma unroll
    for(int j=0;j<4;j++) acc[i][j]=0.0f;

  if(kh==0){
    // Whh k in [0,320), prefetched
    float4 a = *(const float4*)(d_h + (m0+arow)*HH + akq*4);
    float4 w = *(const float4*)(Whh + (size_t)wrow*HH + akq*4);
    for(int k0=0;k0<320;k0+=16){
      As[(akq*4+0)*68+arow]=a.x; As[(akq*4+1)*68+arow]=a.y; As[(akq*4+2)*68+arow]=a.z; As[(akq*4+3)*68+arow]=a.w;
      Ws[(akq*4+0)*68+arow]=w.x; Ws[(akq*4+1)*68+arow]=w.y; Ws[(akq*4+2)*68+arow]=w.z; Ws[(akq*4+3)*68+arow]=w.w;
      __syncthreads();
      if(k0+16<320){
        a = *(const float4*)(d_h + (m0+arow)*HH + k0+16 + akq*4);
        w = *(const float4*)(Whh + (size_t)wrow*HH + k0+16 + akq*4);
      }
#pragma unroll
      for(int kk=0;kk<16;kk++){
        float4 av = *(const float4*)&As[kk*68+tx*4];
        float4 wv = *(const float4*)&Ws[kk*68+ty*4];
        acc[0][0]+=av.x*wv.x; acc[0][1]+=av.x*wv.y; acc[0][2]+=av.x*wv.z; acc[0][3]+=av.x*wv.w;
        acc[1][0]+=av.y*wv.x; acc[1][1]+=av.y*wv.y; acc[1][2]+=av.y*wv.z; acc[1][3]+=av.y*wv.w;
        acc[2][0]+=av.z*wv.x; acc[2][1]+=av.z*wv.y; acc[2][2]+=av.z*wv.z; acc[2][3]+=av.z*wv.w;
        acc[3][0]+=av.w*wv.x; acc[3][1]+=av.w*wv.y; acc[3][2]+=av.w*wv.z; acc[3][3]+=av.w*wv.w;
      }
      __syncthreads();
    }
  } else {
    // Whh k in [320,512), prefetched
    float4 a = *(const float4*)(d_h + (m0+arow)*HH + 320 + akq*4);
    float4 w = *(const float4*)(Whh + (size_t)wrow*HH + 320 + akq*4);
    for(int k0=320;k0<512;k0+=16){
      As[(akq*4+0)*68+arow]=a.x; As[(akq*4+1)*68+arow]=a.y; As[(akq*4+2)*68+arow]=a.z; As[(akq*4+3)*68+arow]=a.w;
      Ws[(akq*4+0)*68+arow]=w.x; Ws[(akq*4+1)*68+arow]=w.y; Ws[(akq*4+2)*68+arow]=w.z; Ws[(akq*4+3)*68+arow]=w.w;
      __syncthreads();
      if(k0+16<512){
        a = *(const float4*)(d_h + (m0+arow)*HH + k0+16 + akq*4);
        w = *(const float4*)(Whh + (size_t)wrow*HH + k0+16 + akq*4);
      }
#pragma unroll
      for(int kk=0;kk<16;kk++){
        float4 av = *(const float4*)&As[kk*68+tx*4];
        float4 wv = *(const float4*)&Ws[kk*68+ty*4];
        acc[0][0]+=av.x*wv.x; acc[0][1]+=av.x*wv.y; acc[0][2]+=av.x*wv.z; acc[0][3]+=av.x*wv.w;
        acc[1][0]+=av.y*wv.x; acc[1][1]+=av.y*wv.y; acc[1][2]+=av.y*wv.z; acc[1][3]+=av.y*wv.w;
        acc[2][0]+=av.z*wv.x; acc[2][1]+=av.z*wv.y; acc[2][2]+=av.z*wv.z; acc[2][3]+=av.z*wv.w;
        acc[3][0]+=av.w*wv.x; acc[3][1]+=av.w*wv.y; acc[3][2]+=av.w*wv.z; acc[3][3]+=av.w*wv.w;
      }
      __syncthreads();
    }
    if(inputs){
      if(tid<64) cities[tid] = inputs[(m0+tid)*SS + t];
      __syncthreads();
    }
    // Wih k in [0,128)
    for(int k0=0;k0<EE;k0+=16){
      const float* xr = inputs ? (embedding + cities[arow]*EE) : (d_decin + (m0+arow)*EE);
      float4 a = *(const float4*)(xr + k0 + akq*4);
      float4 w = *(const float4*)(Wih + (size_t)wrow*EE + k0 + akq*4);
      As[(akq*4+0)*68+arow]=a.x; As[(akq*4+1)*68+arow]=a.y; As[(akq*4+2)*68+arow]=a.z; As[(akq*4+3)*68+arow]=a.w;
      Ws[(akq*4+0)*68+arow]=w.x; Ws[(akq*4+1)*68+arow]=w.y; Ws[(akq*4+2)*68+arow]=w.z; Ws[(akq*4+3)*68+arow]=w.w;
      __syncthreads();
#pragma unroll
      for(int kk=0;kk<16;kk++){
        float4 av = *(const float4*)&As[kk*68+tx*4];
        float4 wv = *(const float4*)&Ws[kk*68+ty*4];
        acc[0][0]+=av.x*wv.x; acc[0][1]+=av.x*wv.y; acc[0][2]+=av.x*wv.z; acc[0][3]+=av.x*wv.w;
        acc[1][0]+=av.y*wv.x; acc[1][1]+=av.y*wv.y; acc[1][2]+=av.y*wv.z; acc[1][3]+=av.y*wv.w;
        acc[2][0]+=av.z*wv.x; acc[2][1]+=av.z*wv.y; acc[2][2]+=av.z*wv.z; acc[2][3]+=av.z*wv.w;
        acc[3][0]+=av.w*wv.x; acc[3][1]+=av.w*wv.y; acc[3][2]+=av.w*wv.z; acc[3][3]+=av.w*wv.w;
      }
      __syncthreads();
    }
  }

  // write partial in gate-major layout
  float* P = kh ? d_gpB : d_gpA;
  const int g   = ty >> 2;
  const int jj  = c*16 + ((ty*4) & 15);
#pragma unroll
  for(int i=0;i<4;i++){
    float4 o; o.x=acc[i][0]; o.y=acc[i][1]; o.z=acc[i][2]; o.w=acc[i][3];
    *(float4*)(P + (size_t)(m0+tx*4+i)*G4 + g*512 + jj) = o;
  }
}

// ---------------- LSTM epilogue: combine gate partials, update c/h ----------------
__device__ __forceinline__ void lstm_epi(const float* __restrict__ bias, int store_enc, int t){
  for(int idx = blockIdx.x*NTHR + threadIdx.x; idx < BB*HH; idx += NBLK*NTHR){
    int b = idx >> 9, j = idx & (HH-1);
    size_t base = (size_t)b*G4;
    float gi = (d_gpA[base +        j] + d_gpB[base +        j]) + bias[j];
    float gf = (d_gpA[base +  512 + j] + d_gpB[base +  512 + j]) + bias[512 + j];
    float gG = (d_gpA[base + 1024 + j] + d_gpB[base + 1024 + j]) + bias[1024 + j];
    float go = (d_gpA[base + 1536 + j] + d_gpB[base + 1536 + j]) + bias[1536 + j];
    float ig = sigm(gi), fg = sigm(gf), gg = tanhf(gG), og = sigm(go);
    float cn = fg * d_c[idx] + ig * gg;
    float hn = og * tanhf(cn);
    d_c[idx] = cn; d_h[idx] = hn;
    if(store_enc) d_encout[((size_t)b*SS + t)*HH + j] = hn;
  }
}

// ---------------- TMA ring: issue one chunk (up to 16 rows x 2KB), 2-buffer ring ----------------
__device__ __forceinline__ void issue16(const float* refbase, const int* sAl, int c, int n,
                                        uint32_t bufu32, uint32_t mb0){
  int bi = c & 1;
  int rows = n - c*16; if(rows > 16) rows = 16;
  uint32_t mb = mb0 + bi*8;
  MBEXPECT(mb, (uint32_t)(rows*2048));
#pragma unroll 1
  for(int r=0;r<rows;r++){
    const float* src = refbase + (size_t)sAl[c*16+r]*HH;
    uint32_t dst = bufu32 + bi*32768 + r*2048;
    BULK_G2S(dst, src, 2048u, mb);
  }
}

// ---------------- THE persistent mega-kernel ----------------
__global__ void __launch_bounds__(NTHR, 2)
pointer_net_kernel(const float* __restrict__ embedding,
                   const float* __restrict__ enc_Wih, const float* __restrict__ enc_Whh, const float* __restrict__ enc_b,
                   const float* __restrict__ dec_Wih, const float* __restrict__ dec_Whh, const float* __restrict__ dec_b,
                   const float* __restrict__ pt_Wq, const float* __restrict__ pt_bq,
                   const float* __restrict__ pt_Wref, const float* __restrict__ pt_bref, const float* __restrict__ pt_V,
                   const float* __restrict__ gl_Wq, const float* __restrict__ gl_bq,
                   const float* __restrict__ gl_Wref, const float* __restrict__ gl_bref, const float* __restrict__ gl_V,
                   const float* __restrict__ dec_start, const int* __restrict__ inputs,
                   float* __restrict__ out, int wr2)
{
  extern __shared__ __align__(128) unsigned char dynsm[];   // 64KB: 2 buffers x 16 rows x 2KB
  __shared__ __align__(16) float shPool[4160];
  __shared__ int shCities[64];
  __shared__ int s_alive[256];
  __shared__ __align__(8) unsigned long long s_mbar[2];
  __shared__ unsigned s_wm[8];
  __shared__ float s_scal[2];
  __shared__ int s_ptr;
  const int tid = threadIdx.x;
  const int bx  = blockIdx.x;
  const uint32_t bufu32 = s2u(dynsm);
  const uint32_t mb0 = s2u(s_mbar);

  // ---- init ----
  for(int i = bx*NTHR + tid; i < BB*HH; i += NBLK*NTHR){
    d_h[i] = 0.0f; d_c[i] = 0.0f;
    if(i < BB*SS)  d_alive[i] = i & (SS-1);
    if(i < BB*EE)  d_decin[i] = dec_start[i & (EE-1)];
  }
  if(tid==0){ for(int i=0;i<2;i++) MBINIT(mb0+i*8, 1); }
  gridsync();

  // ---- encoder (split-k gates + epilogue) ----
  for(int t=0;t<SS;t++){
    gates_part(enc_Whh, enc_Wih, embedding, inputs, t, shPool, shPool+1088, shCities);
    gridsync();
    lstm_epi(enc_b, 1, t);
    gridsync();
  }

  // ---- ref precompute ----
  for(int u = bx; u < 8192; u += NBLK)
    gemm_tile(d_encout, gl_Wref, gl_bref, d_glref, (long)(u>>3)*64, (u&7)*64, shPool, shPool+1088);
  for(int u = bx; u < 8192; u += NBLK)
    gemm_tile(d_encout, pt_Wref, pt_bref, d_ptref, (long)(u>>3)*64, (u&7)*64, shPool, shPool+1088);
  gridsync();

  // ---- decoder ----
  float* sq  = shPool;
  float* sV  = shPool + 512;
  float* sbf = shPool + 1024;
  float* sp  = shPool + 1280;
  float* red = shPool + 1536;
  int*  ridx = (int*)(shPool + 1792);
  const int w = tid>>5, l = tid&31;

  for(int t=0;t<SS;t++){
    const int n  = SS - t;
    const int nc = (n+15)>>4;            // 16-row chunks
    gates_part(dec_Whh, dec_Wih, embedding, nullptr, t, shPool, shPool+1088, shCities);
    gridsync();
    lstm_epi(dec_b, 0, t);
    gridsync();
    gemm_qk8(d_h, gl_Wq, shPool, shPool+1088);   // aq partials (all 256 blocks)
    gridsync();

    const int b = bx;
    const float* glbase = d_glref + (size_t)b*SS*HH;
    const float* ptbase = d_ptref + (size_t)b*SS*HH;

    // ======== GLIMPSE ========
    {
      s_alive[tid] = d_alive[b*SS + tid];
      sq[tid]     = qcombine(b, tid,     gl_bq);
      sq[tid+256] = qcombine(b, tid+256, gl_bq);
      sV[tid] = gl_V[tid];          sV[tid+256] = gl_V[tid+256];
      sbf[tid] = NEGINF;
      __syncthreads();
      if(tid==0){ for(int i=0;i<2;i++){ MBINVAL(mb0+i*8); MBINIT(mb0+i*8, 1); } }
      __syncthreads();
      if(tid==0){ int pre = nc<2?nc:2; for(int c=0;c<pre;c++) issue16(glbase, s_alive, c, n, bufu32, mb0); }
      for(int c=0;c<nc;c++){
        mbwait(mb0+(c&1)*8, (c>>1)&1);
#pragma unroll
        for(int half=0; half<2; half++){
          int ri = c*16 + half*8 + w;
          if(ri < n){
            int s = s_alive[ri];
            const float* rp = (const float*)(dynsm + (size_t)(c&1)*32768 + (size_t)(half*8+w)*2048);
            float acc = 0.0f;
#pragma unroll
            for(int k=0;k<4;k++){
              int j = (k*32 + l)*4;
              float4 rv = *(const float4*)(rp + j);
              acc += tanhf(sq[j+0]+rv.x)*sV[j+0] + tanhf(sq[j+1]+rv.y)*sV[j+1]
                   + tanhf(sq[j+2]+rv.z)*sV[j+2] + tanhf(sq[j+3]+rv.w)*sV[j+3];
            }
            for(int off=16; off; off>>=1) acc += __shfl_down_sync(0xffffffffu, acc, off);
            if(l==0) sbf[s] = acc;
          }
        }
        __syncthreads();
        if(tid==0 && c+2<nc) issue16(glbase, s_alive, c+2, n, bufu32, mb0);
      }
      __syncthreads();
      float x = sbf[tid];
      red[tid]=x; __syncthreads();
      for(int off=128; off; off>>=1){ if(tid<off) red[tid]=fmaxf(red[tid],red[tid+off]); __syncthreads(); }
      if(tid==0) s_scal[0]=red[0]; __syncthreads();
      float e = expf(x - s_scal[0]);
      red[tid]=e; __syncthreads();
      for(int off=128; off; off>>=1){ if(tid<off) red[tid]+=red[tid+off]; __syncthreads(); }
      if(tid==0) s_scal[1]=red[0]; __syncthreads();
      sp[tid] = e / s_scal[1];
      __syncthreads();
      if(tid==0){ for(int i=0;i<2;i++){ MBINVAL(mb0+i*8); MBINIT(mb0+i*8, 1); } }
      __syncthreads();
      if(tid==0){ int pre = nc<2?nc:2; for(int c=0;c<pre;c++) issue16(glbase, s_alive, c, n, bufu32, mb0); }
      float acc0 = 0.0f, acc1 = 0.0f;
      for(int c=0;c<nc;c++){
        mbwait(mb0+(c&1)*8, (c>>1)&1);
        int rows = n - c*16; if(rows > 16) rows = 16;
        const float* bp = (const float*)(dynsm + (size_t)(c&1)*32768);
#pragma unroll 1
        for(int r=0;r<rows;r++){
          float pv = sp[s_alive[c*16+r]];
          acc0 += pv * bp[r*512 + tid];
          acc1 += pv * bp[r*512 + tid + 256];
        }
        __syncthreads();
        if(tid==0 && c+2<nc) issue16(glbase, s_alive, c+2, n, bufu32, mb0);
      }
      d_qv[b*HH + tid]       = acc0;
      d_qv[b*HH + tid + 256] = acc1;
    }
    gridsync();
    gemm_qk8(d_qv, pt_Wq, shPool, shPool+1088);  // ap partials (all 256 blocks)
    gridsync();

    // ======== POINTER + SAMPLE ========
    {
      sq[tid]     = qcombine(b, tid,     pt_bq);
      sq[tid+256] = qcombine(b, tid+256, pt_bq);
      sV[tid] = pt_V[tid];          sV[tid+256] = pt_V[tid+256];
      sbf[tid] = NEGINF;
      __syncthreads();
      if(tid==0){ for(int i=0;i<2;i++){ MBINVAL(mb0+i*8); MBINIT(mb0+i*8, 1); } }
      __syncthreads();
      if(tid==0){ int pre = nc<2?nc:2; for(int c=0;c<pre;c++) issue16(ptbase, s_alive, c, n, bufu32, mb0); }
      for(int c=0;c<nc;c++){
        mbwait(mb0+(c&1)*8, (c>>1)&1);
#pragma unroll
        for(int half=0; half<2; half++){
          int ri = c*16 + half*8 + w;
          if(ri < n){
            int s = s_alive[ri];
            const float* rp = (const float*)(dynsm + (size_t)(c&1)*32768 + (size_t)(half*8+w)*2048);
            float acc = 0.0f;
#pragma unroll
            for(int k=0;k<4;k++){
              int j = (k*32 + l)*4;
              float4 rv = *(const float4*)(rp + j);
              acc += tanhf(sq[j+0]+rv.x)*sV[j+0] + tanhf(sq[j+1]+rv.y)*sV[j+1]
                   + tanhf(sq[j+2]+rv.z)*sV[j+2] + tanhf(sq[j+3]+rv.w)*sV[j+3];
            }
            for(int off=16; off; off>>=1) acc += __shfl_down_sync(0xffffffffu, acc, off);
            if(l==0) sbf[s] = 10.0f * tanhf(acc);
          }
        }
        __syncthreads();
        if(tid==0 && c+2<nc) issue16(ptbase, s_alive, c+2, n, bufu32, mb0);
      }
      __syncthreads();
      float lg = sbf[tid];
      uint32_t a0u,a1u,o0,o1;
      tf2x32(0u, 1u, 0u, (uint32_t)t, a0u, a1u);
      tf2x32(a0u, a1u, 0u, (uint32_t)(b*SS+tid), o0, o1);
      uint32_t bits = o0 ^ o1;
      float u = __uint_as_float((bits>>9) | 0x3f800000u) - 1.0f;
      float gum = -logf(-logf(u + 1e-10f) + 1e-10f);
      float y = lg + gum;
      red[tid]=y; ridx[tid]=tid; __syncthreads();
      for(int off=128; off; off>>=1){
        if(tid<off){
          float v2f=red[tid+off]; int i2=ridx[tid+off];
          if(v2f>red[tid] || (v2f==red[tid] && i2<ridx[tid])){ red[tid]=v2f; ridx[tid]=i2; }
        }
        __syncthreads();
      }
      if(tid==0) s_ptr = ridx[0]; __syncthreads();
      red[tid]=lg; __syncthreads();
      for(int off=128; off; off>>=1){ if(tid<off) red[tid]=fmaxf(red[tid],red[tid+off]); __syncthreads(); }
      if(tid==0) s_scal[0]=red[0]; __syncthreads();
      red[tid]=expf(lg - s_scal[0]); __syncthreads();
      for(int off=128; off; off>>=1){ if(tid<off) red[tid]+=red[tid+off]; __syncthreads(); }
      if(tid==0) s_scal[1]=red[0]; __syncthreads();
      const int ptr = s_ptr;
      if(tid==0){
        float logp = sbf[ptr] - s_scal[0] - logf(s_scal[1]);
        out[b*SS + t] = (float)ptr;
        if(wr2) out[BB*SS + b*SS + t] = logp;
      }
      unsigned aliveb = (sbf[tid] > -1e8f) && (tid != ptr);
      unsigned wm = __ballot_sync(0xffffffffu, aliveb);
      if(l==0) s_wm[w] = wm;
      __syncthreads();
      int rank = __popc(wm & ((l==31)?0x7fffffffu:((1u<<l)-1u)));
      for(int ww=0; ww<w; ww++) rank += __popc(s_wm[ww]);
      if(aliveb) d_alive[b*SS + rank] = tid;
      if(tid < EE){
        int city = inputs[b*SS + ptr];
        d_decin[b*EE + tid] = embedding[city*EE + tid];
      }
    }
    gridsync();
  }
}

extern "C" void kernel_launch(void* const* d_in, const int* in_sizes, int n_in,
                              void* d_out, int out_size) {
  const float* embedding = (const float*)d_in[0];
  const float* enc_Wih   = (const float*)d_in[1];
  const float* enc_Whh   = (const float*)d_in[2];
  const float* enc_b     = (const float*)d_in[3];
  const float* dec_Wih   = (const float*)d_in[4];
  const float* dec_Whh   = (const float*)d_in[5];
  const float* dec_b     = (const float*)d_in[6];
  const float* pt_Wq     = (const float*)d_in[7];
  const float* pt_bq     = (const float*)d_in[8];
  const float* pt_Wref   = (const float*)d_in[9];
  const float* pt_bref   = (const float*)d_in[10];
  const float* pt_V      = (const float*)d_in[11];
  const float* gl_Wq     = (const float*)d_in[12];
  const float* gl_bq     = (const float*)d_in[13];
  const float* gl_Wref   = (const float*)d_in[14];
  const float* gl_bref   = (const float*)d_in[15];
  const float* gl_V      = (const float*)d_in[16];
  const float* dec_start = (const float*)d_in[17];
  const int*   inputs    = (const int*)d_in[18];
  float* out = (float*)d_out;
  int wr2 = (out_size >= 2*BB*SS) ? 1 : 0;

  cudaFuncSetAttribute(pointer_net_kernel, cudaFuncAttributeMaxDynamicSharedMemorySize, 65536);

  pointer_net_kernel<<<NBLK, NTHR, 65536>>>(embedding,
      enc_Wih, enc_Whh, enc_b, dec_Wih, dec_Whh, dec_b,
      pt_Wq, pt_bq, pt_Wref, pt_bref, pt_V,
      gl_Wq, gl_bq, gl_Wref, gl_bref, gl_V,
      dec_start, inputs, out, wr2);
}

// round 11
// speedup vs baseline: 1.0735x; 1.0735x over previous
#include <cuda_runtime.h>
#include <cstdint>
#include <cstddef>

#define BB 256
#define SS 256
#define EE 128
#define HH 512
#define NEGINF (-1e9f)
#define NBLK 256
#define NTHR 256

// ---------------- static device scratch ----------------
__device__ float d_h[BB*HH];
__device__ float d_c[BB*HH];
__device__ float d_encout[BB*SS*HH];
__device__ float d_glref[BB*SS*HH];
__device__ float d_ptref[BB*SS*HH];
__device__ float d_qpart[8*BB*HH];     // split-k partials for q projections
__device__ float d_qv[BB*HH];
__device__ float d_decin[BB*EE];
__device__ int   d_alive[BB*SS];
__device__ unsigned d_barcnt;
__device__ unsigned d_bargen;

__device__ __forceinline__ float sigm(float x){ return 1.0f/(1.0f+expf(-x)); }

__device__ __forceinline__ uint32_t s2u(const void* p){
  uint32_t r;
  asm("{ .reg .u64 t; cvta.to.shared.u64 t, %1; cvt.u32.u64 %0, t; }" : "=r"(r) : "l"(p));
  return r;
}

#define MBINIT(a,c)  asm volatile("mbarrier.init.shared.b64 [%0], %1;" :: "r"(a), "r"(c) : "memory")
#define MBINVAL(a)   asm volatile("mbarrier.inval.shared.b64 [%0];" :: "r"(a) : "memory")
#define MBEXPECT(a,b) asm volatile("mbarrier.arrive.expect_tx.shared.b64 _, [%0], %1;" :: "r"(a), "r"(b) : "memory")
#define BULK_G2S(dst,src,bytes,mbar) \
  asm volatile("cp.async.bulk.shared::cluster.global.mbarrier::complete_tx::bytes [%0], [%1], %2, [%3];" \
               :: "r"(dst), "l"(src), "r"(bytes), "r"(mbar) : "memory")

__device__ __forceinline__ void mbwait(uint32_t a, uint32_t ph){
  uint32_t done;
  asm volatile("{ .reg .pred p; mbarrier.try_wait.parity.acquire.cta.shared::cta.b64 p, [%1], %2; selp.b32 %0,1,0,p; }"
               : "=r"(done) : "r"(a), "r"(ph) : "memory");
  while(!done){
    asm volatile("{ .reg .pred p; mbarrier.try_wait.parity.acquire.cta.shared::cta.b64 p, [%1], %2, 0x989680; selp.b32 %0,1,0,p; }"
                 : "=r"(done) : "r"(a), "r"(ph) : "memory");
  }
}

// Threefry-2x32, 20 rounds (JAX constants)
__device__ __forceinline__ void tf2x32(uint32_t k0, uint32_t k1, uint32_t x0, uint32_t x1,
                                       uint32_t &o0, uint32_t &o1){
  uint32_t k2 = k0 ^ k1 ^ 0x1BD11BDAu;
#define TFR(r) { x0 += x1; x1 = (x1<<(r)) | (x1>>(32-(r))); x1 ^= x0; }
  x0 += k0; x1 += k1;
  TFR(13) TFR(15) TFR(26) TFR(6)
  x0 += k1; x1 += k2 + 1u;
  TFR(17) TFR(29) TFR(16) TFR(24)
  x0 += k2; x1 += k0 + 2u;
  TFR(13) TFR(15) TFR(26) TFR(6)
  x0 += k0; x1 += k1 + 3u;
  TFR(17) TFR(29) TFR(16) TFR(24)
  x0 += k1; x1 += k2 + 4u;
  TFR(13) TFR(15) TFR(26) TFR(6)
  x0 += k2; x1 += k0 + 5u;
#undef TFR
  o0 = x0; o1 = x1;
}

// ---------------- grid-wide barrier ----------------
__device__ __forceinline__ void gridsync(){
  __syncthreads();
  if(threadIdx.x==0){
    unsigned g = *(volatile unsigned*)&d_bargen;
    __threadfence();
    unsigned prev = atomicAdd(&d_barcnt, 1u);
    if(prev == NBLK-1u){
      atomicExch(&d_barcnt, 0u);
      __threadfence();
      atomicExch(&d_bargen, g+1u);
    } else {
      while(*(volatile unsigned*)&d_bargen == g) __nanosleep(32);
      __threadfence();
    }
  }
  __syncthreads();
}

// ---------------- 64x64 tile GEMM (refs), prefetched ----------------
__device__ __forceinline__ void gemm_tile(const float* __restrict__ A, const float* __restrict__ W,
                                          const float* __restrict__ bias, float* __restrict__ C,
                                          long m0, int n0, float* As, float* Ws){
  const int tid  = threadIdx.x;
  const int arow = tid>>2, akq = tid&3;
  const int tx   = tid&15, ty  = tid>>4;
  float acc[4][4];
#pragma unroll
  for(int i=0;i<4;i++)
#pragma unroll
    for(int j=0;j<4;j++) acc[i][j]=0.0f;

  float4 a = *(const float4*)(A + (size_t)(m0+arow)*HH + akq*4);
  float4 w = *(const float4*)(W + (size_t)(n0+arow)*HH + akq*4);
  for(int k0=0;k0<HH;k0+=16){
    As[(akq*4+0)*68+arow]=a.x; As[(akq*4+1)*68+arow]=a.y; As[(akq*4+2)*68+arow]=a.z; As[(akq*4+3)*68+arow]=a.w;
    Ws[(akq*4+0)*68+arow]=w.x; Ws[(akq*4+1)*68+arow]=w.y; Ws[(akq*4+2)*68+arow]=w.z; Ws[(akq*4+3)*68+arow]=w.w;
    __syncthreads();
    if(k0+16<HH){
      a = *(const float4*)(A + (size_t)(m0+arow)*HH + k0+16 + akq*4);
      w = *(const float4*)(W + (size_t)(n0+arow)*HH + k0+16 + akq*4);
    }
#pragma unroll
    for(int kk=0;kk<16;kk++){
      float4 av = *(const float4*)&As[kk*68+tx*4];
      float4 wv = *(const float4*)&Ws[kk*68+ty*4];
      acc[0][0]+=av.x*wv.x; acc[0][1]+=av.x*wv.y; acc[0][2]+=av.x*wv.z; acc[0][3]+=av.x*wv.w;
      acc[1][0]+=av.y*wv.x; acc[1][1]+=av.y*wv.y; acc[1][2]+=av.y*wv.z; acc[1][3]+=av.y*wv.w;
      acc[2][0]+=av.z*wv.x; acc[2][1]+=av.z*wv.y; acc[2][2]+=av.z*wv.z; acc[2][3]+=av.z*wv.w;
      acc[3][0]+=av.w*wv.x; acc[3][1]+=av.w*wv.y; acc[3][2]+=av.w*wv.z; acc[3][3]+=av.w*wv.w;
    }
    __syncthreads();
  }
  const int n = n0 + ty*4;
  float b0=bias[n+0], b1=bias[n+1], b2=bias[n+2], b3=bias[n+3];
#pragma unroll
  for(int i=0;i<4;i++){
    float4 o; o.x=acc[i][0]+b0; o.y=acc[i][1]+b1; o.z=acc[i][2]+b2; o.w=acc[i][3]+b3;
    *(float4*)(C + (size_t)(m0+tx*4+i)*HH + n) = o;
  }
}

// ---------------- q-projection split-k8: 256 blocks, 64x64 tile, k-slice 64 ----------------
__device__ __forceinline__ void gemm_qk8(const float* __restrict__ A, const float* __restrict__ W,
                                         float* As, float* Ws){
  const int tid  = threadIdx.x;
  const int bx   = blockIdx.x;
  const int tt   = bx & 31, kh = bx >> 5;
  const int m0   = (tt>>3)*64, n0 = (tt&7)*64;
  const int kb   = kh*64;
  const int arow = tid>>2, akq = tid&3;
  const int tx   = tid&15, ty  = tid>>4;
  float acc[4][4];
#pragma unroll
  for(int i=0;i<4;i++)
#pragma unroll
    for(int j=0;j<4;j++) acc[i][j]=0.0f;

  for(int k0=kb;k0<kb+64;k0+=16){
    float4 a = *(const float4*)(A + (size_t)(m0+arow)*HH + k0 + akq*4);
    float4 w = *(const float4*)(W + (size_t)(n0+arow)*HH + k0 + akq*4);
    As[(akq*4+0)*68+arow]=a.x; As[(akq*4+1)*68+arow]=a.y; As[(akq*4+2)*68+arow]=a.z; As[(akq*4+3)*68+arow]=a.w;
    Ws[(akq*4+0)*68+arow]=w.x; Ws[(akq*4+1)*68+arow]=w.y; Ws[(akq*4+2)*68+arow]=w.z; Ws[(akq*4+3)*68+arow]=w.w;
    __syncthreads();
#pragma unroll
    for(int kk=0;kk<16;kk++){
      float4 av = *(const float4*)&As[kk*68+tx*4];
      float4 wv = *(const float4*)&Ws[kk*68+ty*4];
      acc[0][0]+=av.x*wv.x; acc[0][1]+=av.x*wv.y; acc[0][2]+=av.x*wv.z; acc[0][3]+=av.x*wv.w;
      acc[1][0]+=av.y*wv.x; acc[1][1]+=av.y*wv.y; acc[1][2]+=av.y*wv.z; acc[1][3]+=av.y*wv.w;
      acc[2][0]+=av.z*wv.x; acc[2][1]+=av.z*wv.y; acc[2][2]+=av.z*wv.z; acc[2][3]+=av.z*wv.w;
      acc[3][0]+=av.w*wv.x; acc[3][1]+=av.w*wv.y; acc[3][2]+=av.w*wv.z; acc[3][3]+=av.w*wv.w;
    }
    __syncthreads();
  }
  float* P = d_qpart + (size_t)kh*(BB*HH);
  const int n = n0 + ty*4;
#pragma unroll
  for(int i=0;i<4;i++){
    float4 o; o.x=acc[i][0]; o.y=acc[i][1]; o.z=acc[i][2]; o.w=acc[i][3];
    *(float4*)(P + (size_t)(m0+tx*4+i)*HH + n) = o;
  }
}

__device__ __forceinline__ float qcombine(int b, int e, const float* __restrict__ bias){
  float v = d_qpart[(size_t)b*HH + e];
#pragma unroll
  for(int kh=1;kh<8;kh++) v += d_qpart[(size_t)kh*(BB*HH) + (size_t)b*HH + e];
  return v + bias[e];
}

// ---------------- fused gates GEMM + LSTM epilogue (R8 version, 128 blocks) ----------------
__device__ __forceinline__ void gates_lstm_tile(const float* __restrict__ Whh, const float* __restrict__ Wih,
                                                const float* __restrict__ bias,
                                                const float* __restrict__ embedding,
                                                const int* __restrict__ inputs, int t, int store_enc,
                                                float* pool, int* cities){
  float* As = pool;
  float* Ws = pool + 1088;
  const int tid  = threadIdx.x;
  const int c    = blockIdx.x & 31;
  const int m0   = (blockIdx.x >> 5) * 64;
  const int arow = tid>>2, akq = tid&3;
  const int tx   = tid&15, ty  = tid>>4;
  const int wrow = ((arow>>4)*512) + c*16 + (arow&15);
  float acc[4][4];
#pragma unroll
  for(int i=0;i<4;i++)
#pragma unroll
    for(int j=0;j<4;j++) acc[i][j]=0.0f;

  // K1 = 512 : h @ Whh^T (prefetched)
  {
    float4 a = *(const float4*)(d_h + (m0+arow)*HH + akq*4);
    float4 w = *(const float4*)(Whh + (size_t)wrow*HH + akq*4);
    for(int k0=0;k0<HH;k0+=16){
      As[(akq*4+0)*68+arow]=a.x; As[(akq*4+1)*68+arow]=a.y; As[(akq*4+2)*68+arow]=a.z; As[(akq*4+3)*68+arow]=a.w;
      Ws[(akq*4+0)*68+arow]=w.x; Ws[(akq*4+1)*68+arow]=w.y; Ws[(akq*4+2)*68+arow]=w.z; Ws[(akq*4+3)*68+arow]=w.w;
      __syncthreads();
      if(k0+16<HH){
        a = *(const float4*)(d_h + (m0+arow)*HH + k0+16 + akq*4);
        w = *(const float4*)(Whh + (size_t)wrow*HH + k0+16 + akq*4);
      }
#pragma unroll
      for(int kk=0;kk<16;kk++){
        float4 av = *(const float4*)&As[kk*68+tx*4];
        float4 wv = *(const float4*)&Ws[kk*68+ty*4];
        acc[0][0]+=av.x*wv.x; acc[0][1]+=av.x*wv.y; acc[0][2]+=av.x*wv.z; acc[0][3]+=av.x*wv.w;
        acc[1][0]+=av.y*wv.x; acc[1][1]+=av.y*wv.y; acc[1][2]+=av.y*wv.z; acc[1][3]+=av.y*wv.w;
        acc[2][0]+=av.z*wv.x; acc[2][1]+=av.z*wv.y; acc[2][2]+=av.z*wv.z; acc[2][3]+=av.z*wv.w;
        acc[3][0]+=av.w*wv.x; acc[3][1]+=av.w*wv.y; acc[3][2]+=av.w*wv.z; acc[3][3]+=av.w*wv.w;
      }
      __syncthreads();
    }
  }

  if(inputs){
    if(tid<64) cities[tid] = inputs[(m0+tid)*SS + t];
    __syncthreads();
  }

  // K2 = 128 : x @ Wih^T
  for(int k0=0;k0<EE;k0+=16){
    const float* xr = inputs ? (embedding + cities[arow]*EE) : (d_decin + (m0+arow)*EE);
    float4 a = *(const float4*)(xr + k0 + akq*4);
    float4 w = *(const float4*)(Wih + (size_t)wrow*EE + k0 + akq*4);
    As[(akq*4+0)*68+arow]=a.x; As[(akq*4+1)*68+arow]=a.y; As[(akq*4+2)*68+arow]=a.z; As[(akq*4+3)*68+arow]=a.w;
    Ws[(akq*4+0)*68+arow]=w.x; Ws[(akq*4+1)*68+arow]=w.y; Ws[(akq*4+2)*68+arow]=w.z; Ws[(akq*4+3)*68+arow]=w.w;
    __syncthreads();
#pragma unroll
    for(int kk=0;kk<16;kk++){
      float4 av = *(const float4*)&As[kk*68+tx*4];
      float4 wv = *(const float4*)&Ws[kk*68+ty*4];
      acc[0][0]+=av.x*wv.x; acc[0][1]+=av.x*wv.y; acc[0][2]+=av.x*wv.z; acc[0][3]+=av.x*wv.w;
      acc[1][0]+=av.y*wv.x; acc[1][1]+=av.y*wv.y; acc[1][2]+=av.y*wv.z; acc[1][3]+=av.y*wv.w;
      acc[2][0]+=av.z*wv.x; acc[2][1]+=av.z*wv.y; acc[2][2]+=av.z*wv.z; acc[2][3]+=av.z*wv.w;
      acc[3][0]+=av.w*wv.x; acc[3][1]+=av.w*wv.y; acc[3][2]+=av.w*wv.z; acc[3][3]+=av.w*wv.w;
    }
    __syncthreads();
  }

  float* T = pool;  // 64 x 65
#pragma unroll
  for(int i=0;i<4;i++){
#pragma unroll
    for(int j2=0;j2<4;j2++){
      int cc = ty*4+j2;
      T[(tx*4+i)*65 + cc] = acc[i][j2] + bias[((cc>>4)*512) + c*16 + (cc&15)];
    }
  }
  __syncthreads();

#pragma unroll
  for(int u=0;u<4;u++){
    int cell = tid + u*256;
    int r = cell>>4, jj = cell&15;
    float ig = sigm(T[r*65+jj]);
    float fg = sigm(T[r*65+16+jj]);
    float gg = tanhf(T[r*65+32+jj]);
    float og = sigm(T[r*65+48+jj]);
    int b = m0 + r, j = c*16 + jj;
    float cn = fg * d_c[b*HH+j] + ig * gg;
    float hn = og * tanhf(cn);
    d_c[b*HH+j] = cn; d_h[b*HH+j] = hn;
    if(store_enc) d_encout[((size_t)b*SS + t)*HH + j] = hn;
  }
}

// ---------------- TMA ring: issue one chunk (up to 16 rows x 2KB), 2-buffer ring ----------------
__device__ __forceinline__ void issue16(const float* refbase, const int* sAl, int c, int n,
                                        uint32_t bufu32, uint32_t mb0){
  int bi = c & 1;
  int rows = n - c*16; if(rows > 16) rows = 16;
  uint32_t mb = mb0 + bi*8;
  MBEXPECT(mb, (uint32_t)(rows*2048));
#pragma unroll 1
  for(int r=0;r<rows;r++){
    const float* src = refbase + (size_t)sAl[c*16+r]*HH;
    uint32_t dst = bufu32 + bi*32768 + r*2048;
    BULK_G2S(dst, src, 2048u, mb);
  }
}

// ---------------- THE persistent mega-kernel ----------------
__global__ void __launch_bounds__(NTHR, 2)
pointer_net_kernel(const float* __restrict__ embedding,
                   const float* __restrict__ enc_Wih, const float* __restrict__ enc_Whh, const float* __restrict__ enc_b,
                   const float* __restrict__ dec_Wih, const float* __restrict__ dec_Whh, const float* __restrict__ dec_b,
                   const float* __restrict__ pt_Wq, const float* __restrict__ pt_bq,
                   const float* __restrict__ pt_Wref, const float* __restrict__ pt_bref, const float* __restrict__ pt_V,
                   const float* __restrict__ gl_Wq, const float* __restrict__ gl_bq,
                   const float* __restrict__ gl_Wref, const float* __restrict__ gl_bref, const float* __restrict__ gl_V,
                   const float* __restrict__ dec_start, const int* __restrict__ inputs,
                   float* __restrict__ out, int wr2)
{
  extern __shared__ __align__(128) unsigned char dynsm[];   // 64KB: 2 buffers x 16 rows x 2KB
  __shared__ __align__(16) float shPool[4160];
  __shared__ int shCities[64];
  __shared__ int s_alive[256];
  __shared__ __align__(8) unsigned long long s_mbar[2];
  __shared__ unsigned s_wm[8];
  __shared__ float s_scal[2];
  __shared__ float schunk[16];
  __shared__ float se[16];
  __shared__ int s_ptr;
  const int tid = threadIdx.x;
  const int bx  = blockIdx.x;
  const uint32_t bufu32 = s2u(dynsm);
  const uint32_t mb0 = s2u(s_mbar);

  // ---- init ----
  for(int i = bx*NTHR + tid; i < BB*HH; i += NBLK*NTHR){
    d_h[i] = 0.0f; d_c[i] = 0.0f;
    if(i < BB*SS)  d_alive[i] = i & (SS-1);
    if(i < BB*EE)  d_decin[i] = dec_start[i & (EE-1)];
  }
  if(tid==0){ for(int i=0;i<2;i++) MBINIT(mb0+i*8, 1); }
  gridsync();

  // ---- encoder ----
  for(int t=0;t<SS;t++){
    if(bx < 128) gates_lstm_tile(enc_Whh, enc_Wih, enc_b, embedding, inputs, t, 1, shPool, shCities);
    gridsync();
  }

  // ---- ref precompute ----
  for(int u = bx; u < 8192; u += NBLK)
    gemm_tile(d_encout, gl_Wref, gl_bref, d_glref, (long)(u>>3)*64, (u&7)*64, shPool, shPool+1088);
  for(int u = bx; u < 8192; u += NBLK)
    gemm_tile(d_encout, pt_Wref, pt_bref, d_ptref, (long)(u>>3)*64, (u&7)*64, shPool, shPool+1088);
  gridsync();

  // ---- decoder ----
  float* sq  = shPool;
  float* sV  = shPool + 512;
  float* sbf = shPool + 1024;
  float* red = shPool + 1536;
  int*  ridx = (int*)(shPool + 1792);
  const int w = tid>>5, l = tid&31;

  for(int t=0;t<SS;t++){
    const int n  = SS - t;
    const int nc = (n+15)>>4;            // 16-row chunks
    if(bx < 128) gates_lstm_tile(dec_Whh, dec_Wih, dec_b, embedding, nullptr, t, 0, shPool, shCities);
    gridsync();
    gemm_qk8(d_h, gl_Wq, shPool, shPool+1088);   // aq partials (all 256 blocks)
    gridsync();

    const int b = bx;
    const float* glbase = d_glref + (size_t)b*SS*HH;
    const float* ptbase = d_ptref + (size_t)b*SS*HH;

    // ======== GLIMPSE: fused logits + online softmax + weighted sum (ONE stream) ========
    {
      s_alive[tid] = d_alive[b*SS + tid];
      sq[tid]     = qcombine(b, tid,     gl_bq);
      sq[tid+256] = qcombine(b, tid+256, gl_bq);
      sV[tid] = gl_V[tid];          sV[tid+256] = gl_V[tid+256];
      __syncthreads();
      if(tid==0){ for(int i=0;i<2;i++){ MBINVAL(mb0+i*8); MBINIT(mb0+i*8, 1); } }
      __syncthreads();
      if(tid==0){ int pre = nc<2?nc:2; for(int c=0;c<pre;c++) issue16(glbase, s_alive, c, n, bufu32, mb0); }
      float Mrun = -1e30f, den = 0.0f, acc0 = 0.0f, acc1 = 0.0f;
      for(int c=0;c<nc;c++){
        mbwait(mb0+(c&1)*8, (c>>1)&1);
        int rows = n - c*16; if(rows > 16) rows = 16;
        // logits for this chunk (warps, tanh-dot over smem rows)
#pragma unroll
        for(int half=0; half<2; half++){
          int ri = c*16 + half*8 + w;
          if(ri < n){
            const float* rp = (const float*)(dynsm + (size_t)(c&1)*32768 + (size_t)(half*8+w)*2048);
            float acc = 0.0f;
#pragma unroll
            for(int k=0;k<4;k++){
              int j = (k*32 + l)*4;
              float4 rv = *(const float4*)(rp + j);
              acc += tanhf(sq[j+0]+rv.x)*sV[j+0] + tanhf(sq[j+1]+rv.y)*sV[j+1]
                   + tanhf(sq[j+2]+rv.z)*sV[j+2] + tanhf(sq[j+3]+rv.w)*sV[j+3];
            }
            for(int off=16; off; off>>=1) acc += __shfl_down_sync(0xffffffffu, acc, off);
            if(l==0) schunk[half*8+w] = acc;
          }
        }
        __syncthreads();
        // online softmax update
        float cmax = -1e30f;
        for(int r=0;r<rows;r++) cmax = fmaxf(cmax, schunk[r]);
        float Mn = fmaxf(Mrun, cmax);
        float scale = expf(Mrun - Mn);
        if(tid < rows) se[tid] = expf(schunk[tid] - Mn);
        __syncthreads();
        const float* bp = (const float*)(dynsm + (size_t)(c&1)*32768);
        acc0 *= scale; acc1 *= scale;
        float sume = 0.0f;
        for(int r=0;r<rows;r++){
          float e = se[r];
          sume += e;
          acc0 += e * bp[r*512 + tid];
          acc1 += e * bp[r*512 + tid + 256];
        }
        den = den*scale + sume;
        Mrun = Mn;
        __syncthreads();
        if(tid==0 && c+2<nc) issue16(glbase, s_alive, c+2, n, bufu32, mb0);
      }
      d_qv[b*HH + tid]       = acc0 / den;
      d_qv[b*HH + tid + 256] = acc1 / den;
    }
    gridsync();
    gemm_qk8(d_qv, pt_Wq, shPool, shPool+1088);  // ap partials (all 256 blocks)
    gridsync();

    // ======== POINTER + SAMPLE ========
    {
      sq[tid]     = qcombine(b, tid,     pt_bq);
      sq[tid+256] = qcombine(b, tid+256, pt_bq);
      sV[tid] = pt_V[tid];          sV[tid+256] = pt_V[tid+256];
      sbf[tid] = NEGINF;
      __syncthreads();
      if(tid==0){ for(int i=0;i<2;i++){ MBINVAL(mb0+i*8); MBINIT(mb0+i*8, 1); } }
      __syncthreads();
      if(tid==0){ int pre = nc<2?nc:2; for(int c=0;c<pre;c++) issue16(ptbase, s_alive, c, n, bufu32, mb0); }
      for(int c=0;c<nc;c++){
        mbwait(mb0+(c&1)*8, (c>>1)&1);
#pragma unroll
        for(int half=0; half<2; half++){
          int ri = c*16 + half*8 + w;
          if(ri < n){
            int s = s_alive[ri];
            const float* rp = (const float*)(dynsm + (size_t)(c&1)*32768 + (size_t)(half*8+w)*2048);
            float acc = 0.0f;
#pragma unroll
            for(int k=0;k<4;k++){
              int j = (k*32 + l)*4;
              float4 rv = *(const float4*)(rp + j);
              acc += tanhf(sq[j+0]+rv.x)*sV[j+0] + tanhf(sq[j+1]+rv.y)*sV[j+1]
                   + tanhf(sq[j+2]+rv.z)*sV[j+2] + tanhf(sq[j+3]+rv.w)*sV[j+3];
            }
            for(int off=16; off; off>>=1) acc += __shfl_down_sync(0xffffffffu, acc, off);
            if(l==0) sbf[s] = 10.0f * tanhf(acc);
          }
        }
        __syncthreads();
        if(tid==0 && c+2<nc) issue16(ptbase, s_alive, c+2, n, bufu32, mb0);
      }
      __syncthreads();
      float lg = sbf[tid];
      uint32_t a0u,a1u,o0,o1;
      tf2x32(0u, 1u, 0u, (uint32_t)t, a0u, a1u);
      tf2x32(a0u, a1u, 0u, (uint32_t)(b*SS+tid), o0, o1);
      uint32_t bits = o0 ^ o1;
      float u = __uint_as_float((bits>>9) | 0x3f800000u) - 1.0f;
      float gum = -logf(-logf(u + 1e-10f) + 1e-10f);
      float y = lg + gum;
      red[tid]=y; ridx[tid]=tid; __syncthreads();
      for(int off=128; off; off>>=1){
        if(tid<off){
          float v2f=red[tid+off]; int i2=ridx[tid+off];
          if(v2f>red[tid] || (v2f==red[tid] && i2<ridx[tid])){ red[tid]=v2f; ridx[tid]=i2; }
        }
        __syncthreads();
      }
      if(tid==0) s_ptr = ridx[0]; __syncthreads();
      red[tid]=lg; __syncthreads();
      for(int off=128; off; off>>=1){ if(tid<off) red[tid]=fmaxf(red[tid],red[tid+off]); __syncthreads(); }
      if(tid==0) s_scal[0]=red[0]; __syncthreads();
      red[tid]=expf(lg - s_scal[0]); __syncthreads();
      for(int off=128; off; off>>=1){ if(tid<off) red[tid]+=red[tid+off]; __syncthreads(); }
      if(tid==0) s_scal[1]=red[0]; __syncthreads();
      const int ptr = s_ptr;
      if(tid==0){
        float logp = sbf[ptr] - s_scal[0] - logf(s_scal[1]);
        out[b*SS + t] = (float)ptr;
        if(wr2) out[BB*SS + b*SS + t] = logp;
      }
      unsigned aliveb = (sbf[tid] > -1e8f) && (tid != ptr);
      unsigned wm = __ballot_sync(0xffffffffu, aliveb);
      if(l==0) s_wm[w] = wm;
      __syncthreads();
      int rank = __popc(wm & ((l==31)?0x7fffffffu:((1u<<l)-1u)));
      for(int ww=0; ww<w; ww++) rank += __popc(s_wm[ww]);
      if(aliveb) d_alive[b*SS + rank] = tid;
      if(tid < EE){
        int city = inputs[b*SS + ptr];
        d_decin[b*EE + tid] = embedding[city*EE + tid];
      }
    }
    gridsync();
  }
}

extern "C" void kernel_launch(void* const* d_in, const int* in_sizes, int n_in,
                              void* d_out, int out_size) {
  const float* embedding = (const float*)d_in[0];
  const float* enc_Wih   = (const float*)d_in[1];
  const float* enc_Whh   = (const float*)d_in[2];
  const float* enc_b     = (const float*)d_in[3];
  const float* dec_Wih   = (const float*)d_in[4];
  const float* dec_Whh   = (const float*)d_in[5];
  const float* dec_b     = (const float*)d_in[6];
  const float* pt_Wq     = (const float*)d_in[7];
  const float* pt_bq     = (const float*)d_in[8];
  const float* pt_Wref   = (const float*)d_in[9];
  const float* pt_bref   = (const float*)d_in[10];
  const float* pt_V      = (const float*)d_in[11];
  const float* gl_Wq     = (const float*)d_in[12];
  const float* gl_bq     = (const float*)d_in[13];
  const float* gl_Wref   = (const float*)d_in[14];
  const float* gl_bref   = (const float*)d_in[15];
  const float* gl_V      = (const float*)d_in[16];
  const float* dec_start = (const float*)d_in[17];
  const int*   inputs    = (const int*)d_in[18];
  float* out = (float*)d_out;
  int wr2 = (out_size >= 2*BB*SS) ? 1 : 0;

  cudaFuncSetAttribute(pointer_net_kernel, cudaFuncAttributeMaxDynamicSharedMemorySize, 65536);

  pointer_net_kernel<<<NBLK, NTHR, 65536>>>(embedding,
      enc_Wih, enc_Whh, enc_b, dec_Wih, dec_Whh, dec_b,
      pt_Wq, pt_bq, pt_Wref, pt_bref, pt_V,
      gl_Wq, gl_bq, gl_Wref, gl_bref, gl_V,
      dec_start, inputs, out, wr2);
}

// round 12
// speedup vs baseline: 1.0739x; 1.0004x over previous
#include <cuda_runtime.h>
#include <cstdint>
#include <cstddef>

#define BB 256
#define SS 256
#define EE 128
#define HH 512
#define NEGINF (-1e9f)
#define NBLK 256
#define NTHR 256

// ---------------- static device scratch ----------------
__device__ float d_h[BB*HH];
__device__ float d_c[BB*HH];
__device__ float d_encout[BB*SS*HH];
__device__ float d_glref[BB*SS*HH];
__device__ float d_ptref[BB*SS*HH];
__device__ float d_qpart[8*BB*HH];     // split-k partials for q projections
__device__ float d_qv[BB*HH];
__device__ float d_decin[BB*EE];
__device__ int   d_alive[BB*SS];
__device__ unsigned d_barcnt;
__device__ unsigned d_bargen;

__device__ __forceinline__ float sigm(float x){ return 1.0f/(1.0f+expf(-x)); }

__device__ __forceinline__ uint32_t s2u(const void* p){
  uint32_t r;
  asm("{ .reg .u64 t; cvta.to.shared.u64 t, %1; cvt.u32.u64 %0, t; }" : "=r"(r) : "l"(p));
  return r;
}

#define MBINIT(a,c)  asm volatile("mbarrier.init.shared.b64 [%0], %1;" :: "r"(a), "r"(c) : "memory")
#define MBINVAL(a)   asm volatile("mbarrier.inval.shared.b64 [%0];" :: "r"(a) : "memory")
#define MBEXPECT(a,b) asm volatile("mbarrier.arrive.expect_tx.shared.b64 _, [%0], %1;" :: "r"(a), "r"(b) : "memory")
#define BULK_G2S(dst,src,bytes,mbar) \
  asm volatile("cp.async.bulk.shared::cluster.global.mbarrier::complete_tx::bytes [%0], [%1], %2, [%3];" \
               :: "r"(dst), "l"(src), "r"(bytes), "r"(mbar) : "memory")

__device__ __forceinline__ void mbwait(uint32_t a, uint32_t ph){
  uint32_t done;
  asm volatile("{ .reg .pred p; mbarrier.try_wait.parity.acquire.cta.shared::cta.b64 p, [%1], %2; selp.b32 %0,1,0,p; }"
               : "=r"(done) : "r"(a), "r"(ph) : "memory");
  while(!done){
    asm volatile("{ .reg .pred p; mbarrier.try_wait.parity.acquire.cta.shared::cta.b64 p, [%1], %2, 0x989680; selp.b32 %0,1,0,p; }"
                 : "=r"(done) : "r"(a), "r"(ph) : "memory");
  }
}

// Threefry-2x32, 20 rounds (JAX constants)
__device__ __forceinline__ void tf2x32(uint32_t k0, uint32_t k1, uint32_t x0, uint32_t x1,
                                       uint32_t &o0, uint32_t &o1){
  uint32_t k2 = k0 ^ k1 ^ 0x1BD11BDAu;
#define TFR(r) { x0 += x1; x1 = (x1<<(r)) | (x1>>(32-(r))); x1 ^= x0; }
  x0 += k0; x1 += k1;
  TFR(13) TFR(15) TFR(26) TFR(6)
  x0 += k1; x1 += k2 + 1u;
  TFR(17) TFR(29) TFR(16) TFR(24)
  x0 += k2; x1 += k0 + 2u;
  TFR(13) TFR(15) TFR(26) TFR(6)
  x0 += k0; x1 += k1 + 3u;
  TFR(17) TFR(29) TFR(16) TFR(24)
  x0 += k1; x1 += k2 + 4u;
  TFR(13) TFR(15) TFR(26) TFR(6)
  x0 += k2; x1 += k0 + 5u;
#undef TFR
  o0 = x0; o1 = x1;
}

// ---------------- grid-wide barrier ----------------
__device__ __forceinline__ void gridsync(){
  __syncthreads();
  if(threadIdx.x==0){
    unsigned g = *(volatile unsigned*)&d_bargen;
    __threadfence();
    unsigned prev = atomicAdd(&d_barcnt, 1u);
    if(prev == NBLK-1u){
      atomicExch(&d_barcnt, 0u);
      __threadfence();
      atomicExch(&d_bargen, g+1u);
    } else {
      while(*(volatile unsigned*)&d_bargen == g) __nanosleep(32);
      __threadfence();
    }
  }
  __syncthreads();
}

// ---------------- 64x64 tile GEMM (refs), prefetched ----------------
__device__ __forceinline__ void gemm_tile(const float* __restrict__ A, const float* __restrict__ W,
                                          const float* __restrict__ bias, float* __restrict__ C,
                                          long m0, int n0, float* As, float* Ws){
  const int tid  = threadIdx.x;
  const int arow = tid>>2, akq = tid&3;
  const int tx   = tid&15, ty  = tid>>4;
  float acc[4][4];
#pragma unroll
  for(int i=0;i<4;i++)
#pragma unroll
    for(int j=0;j<4;j++) acc[i][j]=0.0f;

  float4 a = *(const float4*)(A + (size_t)(m0+arow)*HH + akq*4);
  float4 w = *(const float4*)(W + (size_t)(n0+arow)*HH + akq*4);
  for(int k0=0;k0<HH;k0+=16){
    As[(akq*4+0)*68+arow]=a.x; As[(akq*4+1)*68+arow]=a.y; As[(akq*4+2)*68+arow]=a.z; As[(akq*4+3)*68+arow]=a.w;
    Ws[(akq*4+0)*68+arow]=w.x; Ws[(akq*4+1)*68+arow]=w.y; Ws[(akq*4+2)*68+arow]=w.z; Ws[(akq*4+3)*68+arow]=w.w;
    __syncthreads();
    if(k0+16<HH){
      a = *(const float4*)(A + (size_t)(m0+arow)*HH + k0+16 + akq*4);
      w = *(const float4*)(W + (size_t)(n0+arow)*HH + k0+16 + akq*4);
    }
#pragma unroll
    for(int kk=0;kk<16;kk++){
      float4 av = *(const float4*)&As[kk*68+tx*4];
      float4 wv = *(const float4*)&Ws[kk*68+ty*4];
      acc[0][0]+=av.x*wv.x; acc[0][1]+=av.x*wv.y; acc[0][2]+=av.x*wv.z; acc[0][3]+=av.x*wv.w;
      acc[1][0]+=av.y*wv.x; acc[1][1]+=av.y*wv.y; acc[1][2]+=av.y*wv.z; acc[1][3]+=av.y*wv.w;
      acc[2][0]+=av.z*wv.x; acc[2][1]+=av.z*wv.y; acc[2][2]+=av.z*wv.z; acc[2][3]+=av.z*wv.w;
      acc[3][0]+=av.w*wv.x; acc[3][1]+=av.w*wv.y; acc[3][2]+=av.w*wv.z; acc[3][3]+=av.w*wv.w;
    }
    __syncthreads();
  }
  const int n = n0 + ty*4;
  float b0=bias[n+0], b1=bias[n+1], b2=bias[n+2], b3=bias[n+3];
#pragma unroll
  for(int i=0;i<4;i++){
    float4 o; o.x=acc[i][0]+b0; o.y=acc[i][1]+b1; o.z=acc[i][2]+b2; o.w=acc[i][3]+b3;
    *(float4*)(C + (size_t)(m0+tx*4+i)*HH + n) = o;
  }
}

// ---------------- q-projection split-k8: 256 blocks, 64x64 tile, k-slice 64 ----------------
__device__ __forceinline__ void gemm_qk8(const float* __restrict__ A, const float* __restrict__ W,
                                         float* As, float* Ws){
  const int tid  = threadIdx.x;
  const int bx   = blockIdx.x;
  const int tt   = bx & 31, kh = bx >> 5;
  const int m0   = (tt>>3)*64, n0 = (tt&7)*64;
  const int kb   = kh*64;
  const int arow = tid>>2, akq = tid&3;
  const int tx   = tid&15, ty  = tid>>4;
  float acc[4][4];
#pragma unroll
  for(int i=0;i<4;i++)
#pragma unroll
    for(int j=0;j<4;j++) acc[i][j]=0.0f;

  for(int k0=kb;k0<kb+64;k0+=16){
    float4 a = *(const float4*)(A + (size_t)(m0+arow)*HH + k0 + akq*4);
    float4 w = *(const float4*)(W + (size_t)(n0+arow)*HH + k0 + akq*4);
    As[(akq*4+0)*68+arow]=a.x; As[(akq*4+1)*68+arow]=a.y; As[(akq*4+2)*68+arow]=a.z; As[(akq*4+3)*68+arow]=a.w;
    Ws[(akq*4+0)*68+arow]=w.x; Ws[(akq*4+1)*68+arow]=w.y; Ws[(akq*4+2)*68+arow]=w.z; Ws[(akq*4+3)*68+arow]=w.w;
    __syncthreads();
#pragma unroll
    for(int kk=0;kk<16;kk++){
      float4 av = *(const float4*)&As[kk*68+tx*4];
      float4 wv = *(const float4*)&Ws[kk*68+ty*4];
      acc[0][0]+=av.x*wv.x; acc[0][1]+=av.x*wv.y; acc[0][2]+=av.x*wv.z; acc[0][3]+=av.x*wv.w;
      acc[1][0]+=av.y*wv.x; acc[1][1]+=av.y*wv.y; acc[1][2]+=av.y*wv.z; acc[1][3]+=av.y*wv.w;
      acc[2][0]+=av.z*wv.x; acc[2][1]+=av.z*wv.y; acc[2][2]+=av.z*wv.z; acc[2][3]+=av.z*wv.w;
      acc[3][0]+=av.w*wv.x; acc[3][1]+=av.w*wv.y; acc[3][2]+=av.w*wv.z; acc[3][3]+=av.w*wv.w;
    }
    __syncthreads();
  }
  float* P = d_qpart + (size_t)kh*(BB*HH);
  const int n = n0 + ty*4;
#pragma unroll
  for(int i=0;i<4;i++){
    float4 o; o.x=acc[i][0]; o.y=acc[i][1]; o.z=acc[i][2]; o.w=acc[i][3];
    *(float4*)(P + (size_t)(m0+tx*4+i)*HH + n) = o;
  }
}

__device__ __forceinline__ float qcombine(int b, int e, const float* __restrict__ bias){
  float v = d_qpart[(size_t)b*HH + e];
#pragma unroll
  for(int kh=1;kh<8;kh++) v += d_qpart[(size_t)kh*(BB*HH) + (size_t)b*HH + e];
  return v + bias[e];
}

// ---------------- fused gates GEMM + LSTM epilogue (R8 version, 128 blocks) ----------------
__device__ __forceinline__ void gates_lstm_tile(const float* __restrict__ Whh, const float* __restrict__ Wih,
                                                const float* __restrict__ bias,
                                                const float* __restrict__ embedding,
                                                const int* __restrict__ inputs, int t, int store_enc,
                                                float* pool, int* cities){
  float* As = pool;
  float* Ws = pool + 1088;
  const int tid  = threadIdx.x;
  const int c    = blockIdx.x & 31;
  const int m0   = (blockIdx.x >> 5) * 64;
  const int arow = tid>>2, akq = tid&3;
  const int tx   = tid&15, ty  = tid>>4;
  const int wrow = ((arow>>4)*512) + c*16 + (arow&15);
  float acc[4][4];
#pragma unroll
  for(int i=0;i<4;i++)
#pragma unroll
    for(int j=0;j<4;j++) acc[i][j]=0.0f;

  // K1 = 512 : h @ Whh^T (prefetched)
  {
    float4 a = *(const float4*)(d_h + (m0+arow)*HH + akq*4);
    float4 w = *(const float4*)(Whh + (size_t)wrow*HH + akq*4);
    for(int k0=0;k0<HH;k0+=16){
      As[(akq*4+0)*68+arow]=a.x; As[(akq*4+1)*68+arow]=a.y; As[(akq*4+2)*68+arow]=a.z; As[(akq*4+3)*68+arow]=a.w;
      Ws[(akq*4+0)*68+arow]=w.x; Ws[(akq*4+1)*68+arow]=w.y; Ws[(akq*4+2)*68+arow]=w.z; Ws[(akq*4+3)*68+arow]=w.w;
      __syncthreads();
      if(k0+16<HH){
        a = *(const float4*)(d_h + (m0+arow)*HH + k0+16 + akq*4);
        w = *(const float4*)(Whh + (size_t)wrow*HH + k0+16 + akq*4);
      }
#pragma unroll
      for(int kk=0;kk<16;kk++){
        float4 av = *(const float4*)&As[kk*68+tx*4];
        float4 wv = *(const float4*)&Ws[kk*68+ty*4];
        acc[0][0]+=av.x*wv.x; acc[0][1]+=av.x*wv.y; acc[0][2]+=av.x*wv.z; acc[0][3]+=av.x*wv.w;
        acc[1][0]+=av.y*wv.x; acc[1][1]+=av.y*wv.y; acc[1][2]+=av.y*wv.z; acc[1][3]+=av.y*wv.w;
        acc[2][0]+=av.z*wv.x; acc[2][1]+=av.z*wv.y; acc[2][2]+=av.z*wv.z; acc[2][3]+=av.z*wv.w;
        acc[3][0]+=av.w*wv.x; acc[3][1]+=av.w*wv.y; acc[3][2]+=av.w*wv.z; acc[3][3]+=av.w*wv.w;
      }
      __syncthreads();
    }
  }

  if(inputs){
    if(tid<64) cities[tid] = inputs[(m0+tid)*SS + t];
    __syncthreads();
  }

  // K2 = 128 : x @ Wih^T
  for(int k0=0;k0<EE;k0+=16){
    const float* xr = inputs ? (embedding + cities[arow]*EE) : (d_decin + (m0+arow)*EE);
    float4 a = *(const float4*)(xr + k0 + akq*4);
    float4 w = *(const float4*)(Wih + (size_t)wrow*EE + k0 + akq*4);
    As[(akq*4+0)*68+arow]=a.x; As[(akq*4+1)*68+arow]=a.y; As[(akq*4+2)*68+arow]=a.z; As[(akq*4+3)*68+arow]=a.w;
    Ws[(akq*4+0)*68+arow]=w.x; Ws[(akq*4+1)*68+arow]=w.y; Ws[(akq*4+2)*68+arow]=w.z; Ws[(akq*4+3)*68+arow]=w.w;
    __syncthreads();
#pragma unroll
    for(int kk=0;kk<16;kk++){
      float4 av = *(const float4*)&As[kk*68+tx*4];
      float4 wv = *(const float4*)&Ws[kk*68+ty*4];
      acc[0][0]+=av.x*wv.x; acc[0][1]+=av.x*wv.y; acc[0][2]+=av.x*wv.z; acc[0][3]+=av.x*wv.w;
      acc[1][0]+=av.y*wv.x; acc[1][1]+=av.y*wv.y; acc[1][2]+=av.y*wv.z; acc[1][3]+=av.y*wv.w;
      acc[2][0]+=av.z*wv.x; acc[2][1]+=av.z*wv.y; acc[2][2]+=av.z*wv.z; acc[2][3]+=av.z*wv.w;
      acc[3][0]+=av.w*wv.x; acc[3][1]+=av.w*wv.y; acc[3][2]+=av.w*wv.z; acc[3][3]+=av.w*wv.w;
    }
    __syncthreads();
  }

  float* T = pool;  // 64 x 65
#pragma unroll
  for(int i=0;i<4;i++){
#pragma unroll
    for(int j2=0;j2<4;j2++){
      int cc = ty*4+j2;
      T[(tx*4+i)*65 + cc] = acc[i][j2] + bias[((cc>>4)*512) + c*16 + (cc&15)];
    }
  }
  __syncthreads();

#pragma unroll
  for(int u=0;u<4;u++){
    int cell = tid + u*256;
    int r = cell>>4, jj = cell&15;
    float ig = sigm(T[r*65+jj]);
    float fg = sigm(T[r*65+16+jj]);
    float gg = tanhf(T[r*65+32+jj]);
    float og = sigm(T[r*65+48+jj]);
    int b = m0 + r, j = c*16 + jj;
    float cn = fg * d_c[b*HH+j] + ig * gg;
    float hn = og * tanhf(cn);
    d_c[b*HH+j] = cn; d_h[b*HH+j] = hn;
    if(store_enc) d_encout[((size_t)b*SS + t)*HH + j] = hn;
  }
}

// ---------------- TMA ring: issue one chunk (up to 16 rows x 2KB), 2-buffer ring ----------------
__device__ __forceinline__ void issue16(const float* refbase, const int* sAl, int c, int n,
                                        uint32_t bufu32, uint32_t mb0){
  int bi = c & 1;
  int rows = n - c*16; if(rows > 16) rows = 16;
  uint32_t mb = mb0 + bi*8;
  MBEXPECT(mb, (uint32_t)(rows*2048));
#pragma unroll 1
  for(int r=0;r<rows;r++){
    const float* src = refbase + (size_t)sAl[c*16+r]*HH;
    uint32_t dst = bufu32 + bi*32768 + r*2048;
    BULK_G2S(dst, src, 2048u, mb);
  }
}

// ---------------- THE persistent mega-kernel ----------------
__global__ void __launch_bounds__(NTHR, 2)
pointer_net_kernel(const float* __restrict__ embedding,
                   const float* __restrict__ enc_Wih, const float* __restrict__ enc_Whh, const float* __restrict__ enc_b,
                   const float* __restrict__ dec_Wih, const float* __restrict__ dec_Whh, const float* __restrict__ dec_b,
                   const float* __restrict__ pt_Wq, const float* __restrict__ pt_bq,
                   const float* __restrict__ pt_Wref, const float* __restrict__ pt_bref, const float* __restrict__ pt_V,
                   const float* __restrict__ gl_Wq, const float* __restrict__ gl_bq,
                   const float* __restrict__ gl_Wref, const float* __restrict__ gl_bref, const float* __restrict__ gl_V,
                   const float* __restrict__ dec_start, const int* __restrict__ inputs,
                   float* __restrict__ out, int wr2)
{
  extern __shared__ __align__(128) unsigned char dynsm[];   // 64KB: 2 buffers x 16 rows x 2KB
  __shared__ __align__(16) float shPool[4160];
  __shared__ int shCities[64];
  __shared__ int s_alive[256];
  __shared__ __align__(8) unsigned long long s_mbar[2];
  __shared__ unsigned s_wm[8];
  __shared__ float s_scal[2];
  __shared__ float schunk[16];
  __shared__ float se[16];
  __shared__ int s_ptr;
  const int tid = threadIdx.x;
  const int bx  = blockIdx.x;
  const uint32_t bufu32 = s2u(dynsm);
  const uint32_t mb0 = s2u(s_mbar);

  // ---- init ----
  for(int i = bx*NTHR + tid; i < BB*HH; i += NBLK*NTHR){
    d_h[i] = 0.0f; d_c[i] = 0.0f;
    if(i < BB*SS)  d_alive[i] = i & (SS-1);
    if(i < BB*EE)  d_decin[i] = dec_start[i & (EE-1)];
  }
  if(tid==0){ for(int i=0;i<2;i++) MBINIT(mb0+i*8, 1); }
  gridsync();

  // ---- encoder ----
  for(int t=0;t<SS;t++){
    if(bx < 128) gates_lstm_tile(enc_Whh, enc_Wih, enc_b, embedding, inputs, t, 1, shPool, shCities);
    gridsync();
  }

  // ---- ref precompute ----
  for(int u = bx; u < 8192; u += NBLK)
    gemm_tile(d_encout, gl_Wref, gl_bref, d_glref, (long)(u>>3)*64, (u&7)*64, shPool, shPool+1088);
  for(int u = bx; u < 8192; u += NBLK)
    gemm_tile(d_encout, pt_Wref, pt_bref, d_ptref, (long)(u>>3)*64, (u&7)*64, shPool, shPool+1088);
  gridsync();

  // ---- decoder ----
  float* sq  = shPool;
  float* sV  = shPool + 512;
  float* sbf = shPool + 1024;
  float* red = shPool + 1536;
  int*  ridx = (int*)(shPool + 1792);
  const int w = tid>>5, l = tid&31;

  for(int t=0;t<SS;t++){
    const int n  = SS - t;
    const int nc = (n+15)>>4;            // 16-row chunks
    if(bx < 128) gates_lstm_tile(dec_Whh, dec_Wih, dec_b, embedding, nullptr, t, 0, shPool, shCities);
    gridsync();
    gemm_qk8(d_h, gl_Wq, shPool, shPool+1088);   // aq partials (all 256 blocks)
    gridsync();

    const int b = bx;
    const float* glbase = d_glref + (size_t)b*SS*HH;
    const float* ptbase = d_ptref + (size_t)b*SS*HH;

    // ======== GLIMPSE: fused logits + online softmax + weighted sum (ONE stream) ========
    {
      s_alive[tid] = d_alive[b*SS + tid];
      sq[tid]     = qcombine(b, tid,     gl_bq);
      sq[tid+256] = qcombine(b, tid+256, gl_bq);
      sV[tid] = gl_V[tid];          sV[tid+256] = gl_V[tid+256];
      __syncthreads();
      if(tid==0){ for(int i=0;i<2;i++){ MBINVAL(mb0+i*8); MBINIT(mb0+i*8, 1); } }
      __syncthreads();
      if(tid==0){ int pre = nc<2?nc:2; for(int c=0;c<pre;c++) issue16(glbase, s_alive, c, n, bufu32, mb0); }
      float Mrun = -1e30f, den = 0.0f, acc0 = 0.0f, acc1 = 0.0f;
      for(int c=0;c<nc;c++){
        mbwait(mb0+(c&1)*8, (c>>1)&1);
        int rows = n - c*16; if(rows > 16) rows = 16;
        // logits for this chunk (warps, tanh-dot over smem rows)
#pragma unroll
        for(int half=0; half<2; half++){
          int ri = c*16 + half*8 + w;
          if(ri < n){
            const float* rp = (const float*)(dynsm + (size_t)(c&1)*32768 + (size_t)(half*8+w)*2048);
            float acc = 0.0f;
#pragma unroll
            for(int k=0;k<4;k++){
              int j = (k*32 + l)*4;
              float4 rv = *(const float4*)(rp + j);
              acc += tanhf(sq[j+0]+rv.x)*sV[j+0] + tanhf(sq[j+1]+rv.y)*sV[j+1]
                   + tanhf(sq[j+2]+rv.z)*sV[j+2] + tanhf(sq[j+3]+rv.w)*sV[j+3];
            }
            for(int off=16; off; off>>=1) acc += __shfl_down_sync(0xffffffffu, acc, off);
            if(l==0) schunk[half*8+w] = acc;
          }
        }
        __syncthreads();
        // online softmax update
        float cmax = -1e30f;
        for(int r=0;r<rows;r++) cmax = fmaxf(cmax, schunk[r]);
        float Mn = fmaxf(Mrun, cmax);
        float scale = expf(Mrun - Mn);
        if(tid < rows) se[tid] = expf(schunk[tid] - Mn);
        __syncthreads();
        const float* bp = (const float*)(dynsm + (size_t)(c&1)*32768);
        acc0 *= scale; acc1 *= scale;
        float sume = 0.0f;
        for(int r=0;r<rows;r++){
          float e = se[r];
          sume += e;
          acc0 += e * bp[r*512 + tid];
          acc1 += e * bp[r*512 + tid + 256];
        }
        den = den*scale + sume;
        Mrun = Mn;
        __syncthreads();
        if(tid==0 && c+2<nc) issue16(glbase, s_alive, c+2, n, bufu32, mb0);
      }
      d_qv[b*HH + tid]       = acc0 / den;
      d_qv[b*HH + tid + 256] = acc1 / den;
    }
    gridsync();
    gemm_qk8(d_qv, pt_Wq, shPool, shPool+1088);  // ap partials (all 256 blocks)
    gridsync();

    // ======== POINTER + SAMPLE ========
    {
      sq[tid]     = qcombine(b, tid,     pt_bq);
      sq[tid+256] = qcombine(b, tid+256, pt_bq);
      sV[tid] = pt_V[tid];          sV[tid+256] = pt_V[tid+256];
      sbf[tid] = NEGINF;
      __syncthreads();
      if(tid==0){ for(int i=0;i<2;i++){ MBINVAL(mb0+i*8); MBINIT(mb0+i*8, 1); } }
      __syncthreads();
      if(tid==0){ int pre = nc<2?nc:2; for(int c=0;c<pre;c++) issue16(ptbase, s_alive, c, n, bufu32, mb0); }
      for(int c=0;c<nc;c++){
        mbwait(mb0+(c&1)*8, (c>>1)&1);
#pragma unroll
        for(int half=0; half<2; half++){
          int ri = c*16 + half*8 + w;
          if(ri < n){
            int s = s_alive[ri];
            const float* rp = (const float*)(dynsm + (size_t)(c&1)*32768 + (size_t)(half*8+w)*2048);
            float acc = 0.0f;
#pragma unroll
            for(int k=0;k<4;k++){
              int j = (k*32 + l)*4;
              float4 rv = *(const float4*)(rp + j);
              acc += tanhf(sq[j+0]+rv.x)*sV[j+0] + tanhf(sq[j+1]+rv.y)*sV[j+1]
                   + tanhf(sq[j+2]+rv.z)*sV[j+2] + tanhf(sq[j+3]+rv.w)*sV[j+3];
            }
            for(int off=16; off; off>>=1) acc += __shfl_down_sync(0xffffffffu, acc, off);
            if(l==0) sbf[s] = 10.0f * tanhf(acc);
          }
        }
        __syncthreads();
        if(tid==0 && c+2<nc) issue16(ptbase, s_alive, c+2, n, bufu32, mb0);
      }
      __syncthreads();
      float lg = sbf[tid];
      uint32_t a0u,a1u,o0,o1;
      tf2x32(0u, 1u, 0u, (uint32_t)t, a0u, a1u);
      tf2x32(a0u, a1u, 0u, (uint32_t)(b*SS+tid), o0, o1);
      uint32_t bits = o0 ^ o1;
      float u = __uint_as_float((bits>>9) | 0x3f800000u) - 1.0f;
      float gum = -logf(-logf(u + 1e-10f) + 1e-10f);
      float y = lg + gum;
      red[tid]=y; ridx[tid]=tid; __syncthreads();
      for(int off=128; off; off>>=1){
        if(tid<off){
          float v2f=red[tid+off]; int i2=ridx[tid+off];
          if(v2f>red[tid] || (v2f==red[tid] && i2<ridx[tid])){ red[tid]=v2f; ridx[tid]=i2; }
        }
        __syncthreads();
      }
      if(tid==0) s_ptr = ridx[0]; __syncthreads();
      red[tid]=lg; __syncthreads();
      for(int off=128; off; off>>=1){ if(tid<off) red[tid]=fmaxf(red[tid],red[tid+off]); __syncthreads(); }
      if(tid==0) s_scal[0]=red[0]; __syncthreads();
      red[tid]=expf(lg - s_scal[0]); __syncthreads();
      for(int off=128; off; off>>=1){ if(tid<off) red[tid]+=red[tid+off]; __syncthreads(); }
      if(tid==0) s_scal[1]=red[0]; __syncthreads();
      const int ptr = s_ptr;
      if(tid==0){
        float logp = sbf[ptr] - s_scal[0] - logf(s_scal[1]);
        out[b*SS + t] = (float)ptr;
        if(wr2) out[BB*SS + b*SS + t] = logp;
      }
      unsigned aliveb = (sbf[tid] > -1e8f) && (tid != ptr);
      unsigned wm = __ballot_sync(0xffffffffu, aliveb);
      if(l==0) s_wm[w] = wm;
      __syncthreads();
      int rank = __popc(wm & ((l==31)?0x7fffffffu:((1u<<l)-1u)));
      for(int ww=0; ww<w; ww++) rank += __popc(s_wm[ww]);
      if(aliveb) d_alive[b*SS + rank] = tid;
      if(tid < EE){
        int city = inputs[b*SS + ptr];
        d_decin[b*EE + tid] = embedding[city*EE + tid];
      }
    }
    gridsync();
  }
}

extern "C" void kernel_launch(void* const* d_in, const int* in_sizes, int n_in,
                              void* d_out, int out_size) {
  const float* embedding = (const float*)d_in[0];
  const float* enc_Wih   = (const float*)d_in[1];
  const float* enc_Whh   = (const float*)d_in[2];
  const float* enc_b     = (const float*)d_in[3];
  const float* dec_Wih   = (const float*)d_in[4];
  const float* dec_Whh   = (const float*)d_in[5];
  const float* dec_b     = (const float*)d_in[6];
  const float* pt_Wq     = (const float*)d_in[7];
  const float* pt_bq     = (const float*)d_in[8];
  const float* pt_Wref   = (const float*)d_in[9];
  const float* pt_bref   = (const float*)d_in[10];
  const float* pt_V      = (const float*)d_in[11];
  const float* gl_Wq     = (const float*)d_in[12];
  const float* gl_bq     = (const float*)d_in[13];
  const float* gl_Wref   = (const float*)d_in[14];
  const float* gl_bref   = (const float*)d_in[15];
  const float* gl_V      = (const float*)d_in[16];
  const float* dec_start = (const float*)d_in[17];
  const int*   inputs    = (const int*)d_in[18];
  float* out = (float*)d_out;
  int wr2 = (out_size >= 2*BB*SS) ? 1 : 0;

  cudaFuncSetAttribute(pointer_net_kernel, cudaFuncAttributeMaxDynamicSharedMemorySize, 65536);

  pointer_net_kernel<<<NBLK, NTHR, 65536>>>(embedding,
      enc_Wih, enc_Whh, enc_b, dec_Wih, dec_Whh, dec_b,
      pt_Wq, pt_bq, pt_Wref, pt_bref, pt_V,
      gl_Wq, gl_bq, gl_Wref, gl_bref, gl_V,
      dec_start, inputs, out, wr2);
}